// round 2
// baseline (speedup 1.0000x reference)
#include <cuda_runtime.h>

// ---------------------------------------------------------------------------
// SABlock: causal multi-head self-attention block, fp32.
//   B=4, T=2048, C=1024, H=16, D=64
//   q/k/v = x @ W{q,k,v}^T ; flash-attention (causal) ; out = y @ Wo^T + bo
// Round 0: fp32 FMA baseline. 3 launches. Scratch in __device__ globals.
// ---------------------------------------------------------------------------

#define BB 4
#define TT 2048
#define CC 1024
#define HH 16
#define DD 64
#define MM (BB * TT)        // 8192 rows

// Scratch (static device globals — allocation-free per harness rules)
__device__ __align__(16) float g_Q[BB * HH * TT * DD];
__device__ __align__(16) float g_K[BB * HH * TT * DD];
__device__ __align__(16) float g_V[BB * HH * TT * DD];
__device__ __align__(16) float g_Y[BB * TT * CC];

// ---------------------------------------------------------------------------
// Shared GEMM core: y[m,n] = sum_k A[m,k] * W[n,k]
// Block tile 128x128, K-step 8, 256 threads, 8x8 per-thread microtile.
// ---------------------------------------------------------------------------
__device__ __forceinline__ void gemm128(const float* __restrict__ A,
                                        const float* __restrict__ Wt,
                                        int m0, int n0, float acc[8][8])
{
    __shared__ float As[8][128];
    __shared__ float Bs[8][128];

    const int tid  = threadIdx.x;
    const int lrow = tid >> 1;          // 0..127
    const int lcol = (tid & 1) * 4;     // 0 or 4
    const float* Aptr = A  + (size_t)(m0 + lrow) * CC + lcol;
    const float* Bptr = Wt + (size_t)(n0 + lrow) * CC + lcol;
    const int rm = (tid >> 4) * 8;      // micro row base
    const int cn = (tid & 15) * 8;      // micro col base

    float4 ra = *(const float4*)(Aptr);
    float4 rb = *(const float4*)(Bptr);

    for (int kt = 0; kt < CC / 8; kt++) {
        __syncthreads();
        As[lcol + 0][lrow] = ra.x; As[lcol + 1][lrow] = ra.y;
        As[lcol + 2][lrow] = ra.z; As[lcol + 3][lrow] = ra.w;
        Bs[lcol + 0][lrow] = rb.x; Bs[lcol + 1][lrow] = rb.y;
        Bs[lcol + 2][lrow] = rb.z; Bs[lcol + 3][lrow] = rb.w;
        __syncthreads();
        if (kt + 1 < CC / 8) {
            ra = *(const float4*)(Aptr + (kt + 1) * 8);
            rb = *(const float4*)(Bptr + (kt + 1) * 8);
        }
        #pragma unroll
        for (int k = 0; k < 8; k++) {
            float4 a0 = *(const float4*)&As[k][rm];
            float4 a1 = *(const float4*)&As[k][rm + 4];
            float4 b0 = *(const float4*)&Bs[k][cn];
            float4 b1 = *(const float4*)&Bs[k][cn + 4];
            float av[8] = {a0.x, a0.y, a0.z, a0.w, a1.x, a1.y, a1.z, a1.w};
            float bv[8] = {b0.x, b0.y, b0.z, b0.w, b1.x, b1.y, b1.z, b1.w};
            #pragma unroll
            for (int i = 0; i < 8; i++)
                #pragma unroll
                for (int j = 0; j < 8; j++)
                    acc[i][j] = fmaf(av[i], bv[j], acc[i][j]);
        }
    }
}

// ---------------------------------------------------------------------------
// Kernel 1: fused QKV projection. grid = (N/128=8, M/128=64, 3)
// Epilogue scatters into [B,H,T,D].
// ---------------------------------------------------------------------------
__global__ void __launch_bounds__(256) qkv_kernel(const float* __restrict__ x,
                                                  const float* __restrict__ Wq,
                                                  const float* __restrict__ Wk,
                                                  const float* __restrict__ Wv)
{
    const int z = blockIdx.z;
    const float* W = (z == 0) ? Wq : (z == 1) ? Wk : Wv;
    float* dst     = (z == 0) ? g_Q : (z == 1) ? g_K : g_V;

    const int m0 = blockIdx.y * 128;
    const int n0 = blockIdx.x * 128;

    float acc[8][8];
    #pragma unroll
    for (int i = 0; i < 8; i++)
        #pragma unroll
        for (int j = 0; j < 8; j++) acc[i][j] = 0.f;

    gemm128(x, W, m0, n0, acc);

    const int tid = threadIdx.x;
    const int rm = (tid >> 4) * 8;
    const int cn = (tid & 15) * 8;
    #pragma unroll
    for (int i = 0; i < 8; i++) {
        const int m = m0 + rm + i;
        const int b = m >> 11;          // /T
        const int t = m & (TT - 1);
        #pragma unroll
        for (int jb = 0; jb < 8; jb += 4) {
            const int n = n0 + cn + jb;
            const int h = n >> 6;       // /D
            const int d = n & (DD - 1);
            float4 v = make_float4(acc[i][jb], acc[i][jb + 1], acc[i][jb + 2], acc[i][jb + 3]);
            *(float4*)&dst[((size_t)(b * HH + h) * TT + t) * DD + d] = v;
        }
    }
}

// ---------------------------------------------------------------------------
// Fast exp2 via FMA polynomial (avoids MUFU bottleneck: 134M exps total).
// Valid for t <= ~0.6 (we only call with t <= 0). Max rel err ~2.4e-6.
// ---------------------------------------------------------------------------
__device__ __forceinline__ float fexp2(float t)
{
    t = fmaxf(t, -126.0f);
    float r = t + 12582912.0f;                       // round-to-nearest int
    int   n = __float_as_int(r) - 0x4B400000;        // integer part
    float x = t - (r - 12582912.0f);                 // frac in [-0.5, 0.5]
    float p = 1.33335581e-3f;
    p = fmaf(p, x, 9.61812910e-3f);
    p = fmaf(p, x, 5.55041087e-2f);
    p = fmaf(p, x, 2.40226507e-1f);
    p = fmaf(p, x, 6.93147182e-1f);
    p = fmaf(p, x, 1.0f);
    return p * __int_as_float((n + 127) << 23);
}

// ---------------------------------------------------------------------------
// Kernel 2: causal flash attention. grid = (T/64 = 32 q-tiles, B*H = 64).
// 64x64 q/k tiles, online softmax, O accumulator in registers.
// ---------------------------------------------------------------------------
#define PADW 68
#define SMEM_ATTN_FLOATS (4 * 64 * PADW + 2 * 64 * 17 + 3 * 64)
#define SMEM_ATTN_BYTES  (SMEM_ATTN_FLOATS * 4)

__global__ void __launch_bounds__(256) attn_kernel()
{
    extern __shared__ float sm[];
    float* Qs   = sm;                   // 64 x PADW (pre-scaled)
    float* Ks   = Qs + 64 * PADW;
    float* Vs   = Ks + 64 * PADW;
    float* Ps   = Vs + 64 * PADW;
    float* pmax = Ps + 64 * PADW;       // 64 x 17
    float* psum = pmax + 64 * 17;       // 64 x 17
    float* mrow = psum + 64 * 17;       // 64
    float* lrow = mrow + 64;            // 64
    float* frow = lrow + 64;            // 64

    const int tid = threadIdx.x;
    const int bh  = blockIdx.y;
    const int qi  = gridDim.x - 1 - blockIdx.x;   // big tiles launched first
    const int t0  = qi * 64;
    const float scale = 0.125f;                   // 1/sqrt(64)
    const float LOG2E = 1.4426950408889634f;

    const float* Qg = g_Q + (size_t)bh * TT * DD;
    const float* Kg = g_K + (size_t)bh * TT * DD;
    const float* Vg = g_V + (size_t)bh * TT * DD;

    // Load Q tile (scaled)
    #pragma unroll
    for (int rep = 0; rep < 4; rep++) {
        int lin = rep * 1024 + tid * 4;
        int r = lin >> 6, c = lin & 63;
        float4 v = *(const float4*)&Qg[(size_t)(t0 + r) * DD + c];
        v.x *= scale; v.y *= scale; v.z *= scale; v.w *= scale;
        *(float4*)&Qs[r * PADW + c] = v;
    }
    if (tid < 64) { mrow[tid] = -1e30f; lrow[tid] = 0.f; }

    float o[16];
    #pragma unroll
    for (int i = 0; i < 16; i++) o[i] = 0.f;

    const int tr = tid >> 4, tc = tid & 15;       // S-phase 16x16 thread grid
    const int orow = tid >> 2, cb = (tid & 3) * 16; // PV-phase mapping

    for (int j = 0; j <= qi; j++) {
        __syncthreads();   // prior PV done before overwriting K/V/P
        // Load K and V tiles
        #pragma unroll
        for (int rep = 0; rep < 4; rep++) {
            int lin = rep * 1024 + tid * 4;
            int r = lin >> 6, c = lin & 63;
            *(float4*)&Ks[r * PADW + c] = *(const float4*)&Kg[(size_t)(j * 64 + r) * DD + c];
            *(float4*)&Vs[r * PADW + c] = *(const float4*)&Vg[(size_t)(j * 64 + r) * DD + c];
        }
        __syncthreads();

        // --- S = Qs * Ks^T  (4x4 microtile per thread) ---
        float s[4][4];
        #pragma unroll
        for (int i = 0; i < 4; i++)
            #pragma unroll
            for (int jj = 0; jj < 4; jj++) s[i][jj] = 0.f;

        #pragma unroll 4
        for (int d4 = 0; d4 < 64; d4 += 4) {
            float4 q[4], k[4];
            #pragma unroll
            for (int i = 0; i < 4; i++)
                q[i] = *(const float4*)&Qs[(tr * 4 + i) * PADW + d4];
            #pragma unroll
            for (int jj = 0; jj < 4; jj++)
                k[jj] = *(const float4*)&Ks[(tc * 4 + jj) * PADW + d4];
            #pragma unroll
            for (int i = 0; i < 4; i++)
                #pragma unroll
                for (int jj = 0; jj < 4; jj++) {
                    float acc = s[i][jj];
                    acc = fmaf(q[i].x, k[jj].x, acc);
                    acc = fmaf(q[i].y, k[jj].y, acc);
                    acc = fmaf(q[i].z, k[jj].z, acc);
                    acc = fmaf(q[i].w, k[jj].w, acc);
                    s[i][jj] = acc;
                }
        }
        // causal mask (only the diagonal tile)
        if (j == qi) {
            #pragma unroll
            for (int i = 0; i < 4; i++)
                #pragma unroll
                for (int jj = 0; jj < 4; jj++)
                    if (tc * 4 + jj > tr * 4 + i) s[i][jj] = -1e30f;
        }
        // partial row max
        #pragma unroll
        for (int i = 0; i < 4; i++) {
            float mx = fmaxf(fmaxf(s[i][0], s[i][1]), fmaxf(s[i][2], s[i][3]));
            pmax[(tr * 4 + i) * 17 + tc] = mx;
        }
        __syncthreads();
        if (tid < 64) {
            float mx = pmax[tid * 17];
            #pragma unroll
            for (int t = 1; t < 16; t++) mx = fmaxf(mx, pmax[tid * 17 + t]);
            float mo = mrow[tid];
            float mn = fmaxf(mo, mx);
            mrow[tid] = mn;
            frow[tid] = fexp2((mo - mn) * LOG2E);
        }
        __syncthreads();
        // exponentiate, write P, partial row sums
        #pragma unroll
        for (int i = 0; i < 4; i++) {
            float mn = mrow[tr * 4 + i];
            float rs = 0.f;
            float4 pv;
            pv.x = fexp2((s[i][0] - mn) * LOG2E);
            pv.y = fexp2((s[i][1] - mn) * LOG2E);
            pv.z = fexp2((s[i][2] - mn) * LOG2E);
            pv.w = fexp2((s[i][3] - mn) * LOG2E);
            rs = pv.x + pv.y + pv.z + pv.w;
            *(float4*)&Ps[(tr * 4 + i) * PADW + tc * 4] = pv;
            psum[(tr * 4 + i) * 17 + tc] = rs;
        }
        __syncthreads();
        if (tid < 64) {
            float rs = 0.f;
            #pragma unroll
            for (int t = 0; t < 16; t++) rs += psum[tid * 17 + t];
            lrow[tid] = lrow[tid] * frow[tid] + rs;
        }
        // --- rescale accumulator and O += P * V ---
        float f = frow[orow];
        #pragma unroll
        for (int i = 0; i < 16; i++) o[i] *= f;

        #pragma unroll 8
        for (int kk = 0; kk < 64; kk++) {
            float p = Ps[orow * PADW + kk];
            float4 v0 = *(const float4*)&Vs[kk * PADW + cb];
            float4 v1 = *(const float4*)&Vs[kk * PADW + cb + 4];
            float4 v2 = *(const float4*)&Vs[kk * PADW + cb + 8];
            float4 v3 = *(const float4*)&Vs[kk * PADW + cb + 12];
            o[0]  = fmaf(p, v0.x, o[0]);  o[1]  = fmaf(p, v0.y, o[1]);
            o[2]  = fmaf(p, v0.z, o[2]);  o[3]  = fmaf(p, v0.w, o[3]);
            o[4]  = fmaf(p, v1.x, o[4]);  o[5]  = fmaf(p, v1.y, o[5]);
            o[6]  = fmaf(p, v1.z, o[6]);  o[7]  = fmaf(p, v1.w, o[7]);
            o[8]  = fmaf(p, v2.x, o[8]);  o[9]  = fmaf(p, v2.y, o[9]);
            o[10] = fmaf(p, v2.z, o[10]); o[11] = fmaf(p, v2.w, o[11]);
            o[12] = fmaf(p, v3.x, o[12]); o[13] = fmaf(p, v3.y, o[13]);
            o[14] = fmaf(p, v3.z, o[14]); o[15] = fmaf(p, v3.w, o[15]);
        }
    }
    __syncthreads();   // lrow final values visible to all

    // epilogue: normalize, merge heads into g_Y [B,T,C]
    const float linv = 1.0f / lrow[orow];
    const int b = bh >> 4, h = bh & 15;
    float* yrow = g_Y + ((size_t)(b * TT + t0 + orow)) * CC + h * 64 + cb;
    #pragma unroll
    for (int g = 0; g < 4; g++) {
        float4 w = make_float4(o[g * 4] * linv, o[g * 4 + 1] * linv,
                               o[g * 4 + 2] * linv, o[g * 4 + 3] * linv);
        *(float4*)&yrow[g * 4] = w;
    }
}

// ---------------------------------------------------------------------------
// Kernel 3: output projection  out = Y @ Wo^T + bo.  grid = (8, 64)
// ---------------------------------------------------------------------------
__global__ void __launch_bounds__(256) outproj_kernel(const float* __restrict__ Wo,
                                                      const float* __restrict__ bo,
                                                      float* __restrict__ out)
{
    const int m0 = blockIdx.y * 128;
    const int n0 = blockIdx.x * 128;

    float acc[8][8];
    #pragma unroll
    for (int i = 0; i < 8; i++)
        #pragma unroll
        for (int j = 0; j < 8; j++) acc[i][j] = 0.f;

    gemm128(g_Y, Wo, m0, n0, acc);

    const int tid = threadIdx.x;
    const int rm = (tid >> 4) * 8;
    const int cn = (tid & 15) * 8;
    #pragma unroll
    for (int i = 0; i < 8; i++) {
        const int m = m0 + rm + i;
        #pragma unroll
        for (int jb = 0; jb < 8; jb += 4) {
            const int n = n0 + cn + jb;
            float4 bias = *(const float4*)&bo[n];
            float4 v = make_float4(acc[i][jb] + bias.x, acc[i][jb + 1] + bias.y,
                                   acc[i][jb + 2] + bias.z, acc[i][jb + 3] + bias.w);
            *(float4*)&out[(size_t)m * CC + n] = v;
        }
    }
}

// ---------------------------------------------------------------------------
// Launch
// ---------------------------------------------------------------------------
extern "C" void kernel_launch(void* const* d_in, const int* in_sizes, int n_in,
                              void* d_out, int out_size)
{
    const float* x  = (const float*)d_in[0];
    const float* Wq = (const float*)d_in[1];
    const float* Wk = (const float*)d_in[2];
    const float* Wv = (const float*)d_in[3];
    const float* Wo = (const float*)d_in[4];
    const float* bo = (const float*)d_in[5];
    float* out = (float*)d_out;

    cudaFuncSetAttribute(attn_kernel, cudaFuncAttributeMaxDynamicSharedMemorySize,
                         SMEM_ATTN_BYTES);

    qkv_kernel<<<dim3(8, 64, 3), 256>>>(x, Wq, Wk, Wv);
    attn_kernel<<<dim3(32, 64), 256, SMEM_ATTN_BYTES>>>();
    outproj_kernel<<<dim3(8, 64), 256>>>(Wo, bo, out);
}

// round 3
// speedup vs baseline: 1.0030x; 1.0030x over previous
#include <cuda_runtime.h>

// ---------------------------------------------------------------------------
// SABlock: causal multi-head self-attention block, fp32.
//   B=4, T=2048, C=1024, H=16, D=64
//   q/k/v = x @ W{q,k,v}^T ; flash-attention (causal) ; out = y @ Wo^T + bo
// Round 0: fp32 FMA baseline. 3 launches. Scratch in __device__ globals.
// ---------------------------------------------------------------------------

#define BB 4
#define TT 2048
#define CC 1024
#define HH 16
#define DD 64
#define MM (BB * TT)        // 8192 rows

// Scratch (static device globals — allocation-free per harness rules)
__device__ __align__(16) float g_Q[BB * HH * TT * DD];
__device__ __align__(16) float g_K[BB * HH * TT * DD];
__device__ __align__(16) float g_V[BB * HH * TT * DD];
__device__ __align__(16) float g_Y[BB * TT * CC];

// ---------------------------------------------------------------------------
// Shared GEMM core: y[m,n] = sum_k A[m,k] * W[n,k]
// Block tile 128x128, K-step 8, 256 threads, 8x8 per-thread microtile.
// ---------------------------------------------------------------------------
__device__ __forceinline__ void gemm128(const float* __restrict__ A,
                                        const float* __restrict__ Wt,
                                        int m0, int n0, float acc[8][8])
{
    __shared__ float As[8][128];
    __shared__ float Bs[8][128];

    const int tid  = threadIdx.x;
    const int lrow = tid >> 1;          // 0..127
    const int lcol = (tid & 1) * 4;     // 0 or 4
    const float* Aptr = A  + (size_t)(m0 + lrow) * CC + lcol;
    const float* Bptr = Wt + (size_t)(n0 + lrow) * CC + lcol;
    const int rm = (tid >> 4) * 8;      // micro row base
    const int cn = (tid & 15) * 8;      // micro col base

    float4 ra = *(const float4*)(Aptr);
    float4 rb = *(const float4*)(Bptr);

    for (int kt = 0; kt < CC / 8; kt++) {
        __syncthreads();
        As[lcol + 0][lrow] = ra.x; As[lcol + 1][lrow] = ra.y;
        As[lcol + 2][lrow] = ra.z; As[lcol + 3][lrow] = ra.w;
        Bs[lcol + 0][lrow] = rb.x; Bs[lcol + 1][lrow] = rb.y;
        Bs[lcol + 2][lrow] = rb.z; Bs[lcol + 3][lrow] = rb.w;
        __syncthreads();
        if (kt + 1 < CC / 8) {
            ra = *(const float4*)(Aptr + (kt + 1) * 8);
            rb = *(const float4*)(Bptr + (kt + 1) * 8);
        }
        #pragma unroll
        for (int k = 0; k < 8; k++) {
            float4 a0 = *(const float4*)&As[k][rm];
            float4 a1 = *(const float4*)&As[k][rm + 4];
            float4 b0 = *(const float4*)&Bs[k][cn];
            float4 b1 = *(const float4*)&Bs[k][cn + 4];
            float av[8] = {a0.x, a0.y, a0.z, a0.w, a1.x, a1.y, a1.z, a1.w};
            float bv[8] = {b0.x, b0.y, b0.z, b0.w, b1.x, b1.y, b1.z, b1.w};
            #pragma unroll
            for (int i = 0; i < 8; i++)
                #pragma unroll
                for (int j = 0; j < 8; j++)
                    acc[i][j] = fmaf(av[i], bv[j], acc[i][j]);
        }
    }
}

// ---------------------------------------------------------------------------
// Kernel 1: fused QKV projection. grid = (N/128=8, M/128=64, 3)
// Epilogue scatters into [B,H,T,D].
// ---------------------------------------------------------------------------
__global__ void __launch_bounds__(256) qkv_kernel(const float* __restrict__ x,
                                                  const float* __restrict__ Wq,
                                                  const float* __restrict__ Wk,
                                                  const float* __restrict__ Wv)
{
    const int z = blockIdx.z;
    const float* W = (z == 0) ? Wq : (z == 1) ? Wk : Wv;
    float* dst     = (z == 0) ? g_Q : (z == 1) ? g_K : g_V;

    const int m0 = blockIdx.y * 128;
    const int n0 = blockIdx.x * 128;

    float acc[8][8];
    #pragma unroll
    for (int i = 0; i < 8; i++)
        #pragma unroll
        for (int j = 0; j < 8; j++) acc[i][j] = 0.f;

    gemm128(x, W, m0, n0, acc);

    const int tid = threadIdx.x;
    const int rm = (tid >> 4) * 8;
    const int cn = (tid & 15) * 8;
    #pragma unroll
    for (int i = 0; i < 8; i++) {
        const int m = m0 + rm + i;
        const int b = m >> 11;          // /T
        const int t = m & (TT - 1);
        #pragma unroll
        for (int jb = 0; jb < 8; jb += 4) {
            const int n = n0 + cn + jb;
            const int h = n >> 6;       // /D
            const int d = n & (DD - 1);
            float4 v = make_float4(acc[i][jb], acc[i][jb + 1], acc[i][jb + 2], acc[i][jb + 3]);
            *(float4*)&dst[((size_t)(b * HH + h) * TT + t) * DD + d] = v;
        }
    }
}

// ---------------------------------------------------------------------------
// Fast exp2 via FMA polynomial (avoids MUFU bottleneck: 134M exps total).
// Valid for t <= ~0.6 (we only call with t <= 0). Max rel err ~2.4e-6.
// ---------------------------------------------------------------------------
__device__ __forceinline__ float fexp2(float t)
{
    t = fmaxf(t, -126.0f);
    float r = t + 12582912.0f;                       // round-to-nearest int
    int   n = __float_as_int(r) - 0x4B400000;        // integer part
    float x = t - (r - 12582912.0f);                 // frac in [-0.5, 0.5]
    float p = 1.33335581e-3f;
    p = fmaf(p, x, 9.61812910e-3f);
    p = fmaf(p, x, 5.55041087e-2f);
    p = fmaf(p, x, 2.40226507e-1f);
    p = fmaf(p, x, 6.93147182e-1f);
    p = fmaf(p, x, 1.0f);
    return p * __int_as_float((n + 127) << 23);
}

// ---------------------------------------------------------------------------
// Kernel 2: causal flash attention. grid = (T/64 = 32 q-tiles, B*H = 64).
// 64x64 q/k tiles, online softmax, O accumulator in registers.
// ---------------------------------------------------------------------------
#define PADW 68
#define SMEM_ATTN_FLOATS (4 * 64 * PADW + 2 * 64 * 17 + 3 * 64)
#define SMEM_ATTN_BYTES  (SMEM_ATTN_FLOATS * 4)

__global__ void __launch_bounds__(256) attn_kernel()
{
    extern __shared__ float sm[];
    float* Qs   = sm;                   // 64 x PADW (pre-scaled)
    float* Ks   = Qs + 64 * PADW;
    float* Vs   = Ks + 64 * PADW;
    float* Ps   = Vs + 64 * PADW;
    float* pmax = Ps + 64 * PADW;       // 64 x 17
    float* psum = pmax + 64 * 17;       // 64 x 17
    float* mrow = psum + 64 * 17;       // 64
    float* lrow = mrow + 64;            // 64
    float* frow = lrow + 64;            // 64

    const int tid = threadIdx.x;
    const int bh  = blockIdx.y;
    const int qi  = gridDim.x - 1 - blockIdx.x;   // big tiles launched first
    const int t0  = qi * 64;
    const float scale = 0.125f;                   // 1/sqrt(64)
    const float LOG2E = 1.4426950408889634f;

    const float* Qg = g_Q + (size_t)bh * TT * DD;
    const float* Kg = g_K + (size_t)bh * TT * DD;
    const float* Vg = g_V + (size_t)bh * TT * DD;

    // Load Q tile (scaled)
    #pragma unroll
    for (int rep = 0; rep < 4; rep++) {
        int lin = rep * 1024 + tid * 4;
        int r = lin >> 6, c = lin & 63;
        float4 v = *(const float4*)&Qg[(size_t)(t0 + r) * DD + c];
        v.x *= scale; v.y *= scale; v.z *= scale; v.w *= scale;
        *(float4*)&Qs[r * PADW + c] = v;
    }
    if (tid < 64) { mrow[tid] = -1e30f; lrow[tid] = 0.f; }

    float o[16];
    #pragma unroll
    for (int i = 0; i < 16; i++) o[i] = 0.f;

    const int tr = tid >> 4, tc = tid & 15;       // S-phase 16x16 thread grid
    const int orow = tid >> 2, cb = (tid & 3) * 16; // PV-phase mapping

    for (int j = 0; j <= qi; j++) {
        __syncthreads();   // prior PV done before overwriting K/V/P
        // Load K and V tiles
        #pragma unroll
        for (int rep = 0; rep < 4; rep++) {
            int lin = rep * 1024 + tid * 4;
            int r = lin >> 6, c = lin & 63;
            *(float4*)&Ks[r * PADW + c] = *(const float4*)&Kg[(size_t)(j * 64 + r) * DD + c];
            *(float4*)&Vs[r * PADW + c] = *(const float4*)&Vg[(size_t)(j * 64 + r) * DD + c];
        }
        __syncthreads();

        // --- S = Qs * Ks^T  (4x4 microtile per thread) ---
        float s[4][4];
        #pragma unroll
        for (int i = 0; i < 4; i++)
            #pragma unroll
            for (int jj = 0; jj < 4; jj++) s[i][jj] = 0.f;

        #pragma unroll 4
        for (int d4 = 0; d4 < 64; d4 += 4) {
            float4 q[4], k[4];
            #pragma unroll
            for (int i = 0; i < 4; i++)
                q[i] = *(const float4*)&Qs[(tr * 4 + i) * PADW + d4];
            #pragma unroll
            for (int jj = 0; jj < 4; jj++)
                k[jj] = *(const float4*)&Ks[(tc * 4 + jj) * PADW + d4];
            #pragma unroll
            for (int i = 0; i < 4; i++)
                #pragma unroll
                for (int jj = 0; jj < 4; jj++) {
                    float acc = s[i][jj];
                    acc = fmaf(q[i].x, k[jj].x, acc);
                    acc = fmaf(q[i].y, k[jj].y, acc);
                    acc = fmaf(q[i].z, k[jj].z, acc);
                    acc = fmaf(q[i].w, k[jj].w, acc);
                    s[i][jj] = acc;
                }
        }
        // causal mask (only the diagonal tile)
        if (j == qi) {
            #pragma unroll
            for (int i = 0; i < 4; i++)
                #pragma unroll
                for (int jj = 0; jj < 4; jj++)
                    if (tc * 4 + jj > tr * 4 + i) s[i][jj] = -1e30f;
        }
        // partial row max
        #pragma unroll
        for (int i = 0; i < 4; i++) {
            float mx = fmaxf(fmaxf(s[i][0], s[i][1]), fmaxf(s[i][2], s[i][3]));
            pmax[(tr * 4 + i) * 17 + tc] = mx;
        }
        __syncthreads();
        if (tid < 64) {
            float mx = pmax[tid * 17];
            #pragma unroll
            for (int t = 1; t < 16; t++) mx = fmaxf(mx, pmax[tid * 17 + t]);
            float mo = mrow[tid];
            float mn = fmaxf(mo, mx);
            mrow[tid] = mn;
            frow[tid] = fexp2((mo - mn) * LOG2E);
        }
        __syncthreads();
        // exponentiate, write P, partial row sums
        #pragma unroll
        for (int i = 0; i < 4; i++) {
            float mn = mrow[tr * 4 + i];
            float rs = 0.f;
            float4 pv;
            pv.x = fexp2((s[i][0] - mn) * LOG2E);
            pv.y = fexp2((s[i][1] - mn) * LOG2E);
            pv.z = fexp2((s[i][2] - mn) * LOG2E);
            pv.w = fexp2((s[i][3] - mn) * LOG2E);
            rs = pv.x + pv.y + pv.z + pv.w;
            *(float4*)&Ps[(tr * 4 + i) * PADW + tc * 4] = pv;
            psum[(tr * 4 + i) * 17 + tc] = rs;
        }
        __syncthreads();
        if (tid < 64) {
            float rs = 0.f;
            #pragma unroll
            for (int t = 0; t < 16; t++) rs += psum[tid * 17 + t];
            lrow[tid] = lrow[tid] * frow[tid] + rs;
        }
        // --- rescale accumulator and O += P * V ---
        float f = frow[orow];
        #pragma unroll
        for (int i = 0; i < 16; i++) o[i] *= f;

        #pragma unroll 8
        for (int kk = 0; kk < 64; kk++) {
            float p = Ps[orow * PADW + kk];
            float4 v0 = *(const float4*)&Vs[kk * PADW + cb];
            float4 v1 = *(const float4*)&Vs[kk * PADW + cb + 4];
            float4 v2 = *(const float4*)&Vs[kk * PADW + cb + 8];
            float4 v3 = *(const float4*)&Vs[kk * PADW + cb + 12];
            o[0]  = fmaf(p, v0.x, o[0]);  o[1]  = fmaf(p, v0.y, o[1]);
            o[2]  = fmaf(p, v0.z, o[2]);  o[3]  = fmaf(p, v0.w, o[3]);
            o[4]  = fmaf(p, v1.x, o[4]);  o[5]  = fmaf(p, v1.y, o[5]);
            o[6]  = fmaf(p, v1.z, o[6]);  o[7]  = fmaf(p, v1.w, o[7]);
            o[8]  = fmaf(p, v2.x, o[8]);  o[9]  = fmaf(p, v2.y, o[9]);
            o[10] = fmaf(p, v2.z, o[10]); o[11] = fmaf(p, v2.w, o[11]);
            o[12] = fmaf(p, v3.x, o[12]); o[13] = fmaf(p, v3.y, o[13]);
            o[14] = fmaf(p, v3.z, o[14]); o[15] = fmaf(p, v3.w, o[15]);
        }
    }
    __syncthreads();   // lrow final values visible to all

    // epilogue: normalize, merge heads into g_Y [B,T,C]
    const float linv = 1.0f / lrow[orow];
    const int b = bh >> 4, h = bh & 15;
    float* yrow = g_Y + ((size_t)(b * TT + t0 + orow)) * CC + h * 64 + cb;
    #pragma unroll
    for (int g = 0; g < 4; g++) {
        float4 w = make_float4(o[g * 4] * linv, o[g * 4 + 1] * linv,
                               o[g * 4 + 2] * linv, o[g * 4 + 3] * linv);
        *(float4*)&yrow[g * 4] = w;
    }
}

// ---------------------------------------------------------------------------
// Kernel 3: output projection  out = Y @ Wo^T + bo.  grid = (8, 64)
// ---------------------------------------------------------------------------
__global__ void __launch_bounds__(256) outproj_kernel(const float* __restrict__ Wo,
                                                      const float* __restrict__ bo,
                                                      float* __restrict__ out)
{
    const int m0 = blockIdx.y * 128;
    const int n0 = blockIdx.x * 128;

    float acc[8][8];
    #pragma unroll
    for (int i = 0; i < 8; i++)
        #pragma unroll
        for (int j = 0; j < 8; j++) acc[i][j] = 0.f;

    gemm128(g_Y, Wo, m0, n0, acc);

    const int tid = threadIdx.x;
    const int rm = (tid >> 4) * 8;
    const int cn = (tid & 15) * 8;
    #pragma unroll
    for (int i = 0; i < 8; i++) {
        const int m = m0 + rm + i;
        #pragma unroll
        for (int jb = 0; jb < 8; jb += 4) {
            const int n = n0 + cn + jb;
            float4 bias = *(const float4*)&bo[n];
            float4 v = make_float4(acc[i][jb] + bias.x, acc[i][jb + 1] + bias.y,
                                   acc[i][jb + 2] + bias.z, acc[i][jb + 3] + bias.w);
            *(float4*)&out[(size_t)m * CC + n] = v;
        }
    }
}

// ---------------------------------------------------------------------------
// Launch
// ---------------------------------------------------------------------------
extern "C" void kernel_launch(void* const* d_in, const int* in_sizes, int n_in,
                              void* d_out, int out_size)
{
    const float* x  = (const float*)d_in[0];
    const float* Wq = (const float*)d_in[1];
    const float* Wk = (const float*)d_in[2];
    const float* Wv = (const float*)d_in[3];
    const float* Wo = (const float*)d_in[4];
    const float* bo = (const float*)d_in[5];
    float* out = (float*)d_out;

    cudaFuncSetAttribute(attn_kernel, cudaFuncAttributeMaxDynamicSharedMemorySize,
                         SMEM_ATTN_BYTES);

    qkv_kernel<<<dim3(8, 64, 3), 256>>>(x, Wq, Wk, Wv);
    attn_kernel<<<dim3(32, 64), 256, SMEM_ATTN_BYTES>>>();
    outproj_kernel<<<dim3(8, 64), 256>>>(Wo, bo, out);
}

// round 5
// speedup vs baseline: 4.6569x; 4.6429x over previous
#include <cuda_runtime.h>
#include <cstdint>

// ---------------------------------------------------------------------------
// SABlock: causal MHA block. B=4, T=2048, C=1024, H=16, D=64.
// Round 4: tensor cores via mma.sync tf32 + ldmatrix (cvt.rna.tf32 fixed:
// destination must be a .b32 register, not .f32).
// ---------------------------------------------------------------------------

#define BB 4
#define TT 2048
#define CC 1024
#define HH 16
#define DD 64

__device__ __align__(16) float g_Q[BB * HH * TT * DD];
__device__ __align__(16) float g_K[BB * HH * TT * DD];
__device__ __align__(16) float g_V[BB * HH * TT * DD];
__device__ __align__(16) float g_Y[BB * TT * CC];

__device__ __forceinline__ float to_tf32(float x) {
    uint32_t u;
    asm("cvt.rna.tf32.f32 %0, %1;" : "=r"(u) : "f"(x));
    return __uint_as_float(u);
}
__device__ __forceinline__ uint32_t smem_u32(const void* p) {
    return (uint32_t)__cvta_generic_to_shared(p);
}

#define LDSM4(r, addr)                                                        \
    asm volatile("ldmatrix.sync.aligned.m8n8.x4.shared.b16 {%0,%1,%2,%3}, [%4];" \
                 : "=r"((r)[0]), "=r"((r)[1]), "=r"((r)[2]), "=r"((r)[3])     \
                 : "r"(addr))

#define MMA_TF32(c, a, b0_, b1_)                                              \
    asm volatile("mma.sync.aligned.m16n8k8.row.col.f32.tf32.tf32.f32 "        \
                 "{%0,%1,%2,%3},{%4,%5,%6,%7},{%8,%9},{%0,%1,%2,%3};"         \
                 : "+f"((c)[0]), "+f"((c)[1]), "+f"((c)[2]), "+f"((c)[3])     \
                 : "r"((a)[0]), "r"((a)[1]), "r"((a)[2]), "r"((a)[3]),        \
                   "r"(b0_), "r"(b1_))

// ---------------------------------------------------------------------------
// tf32 GEMM core: y[m,n] = sum_k A[m,k] * W[n,k].
// 128x128x16 tiles, 256 threads (8 warps, 4M x 2N), warp tile 32x64.
// Smem rows padded to 20 floats -> conflict-free ldmatrix for A and B frags.
// ---------------------------------------------------------------------------
__device__ __forceinline__ void gemm_tf32(const float* __restrict__ A,
                                          const float* __restrict__ W,
                                          int m0, int n0, float acc[2][8][4])
{
    __shared__ float As[128][20];
    __shared__ float Bs[128][20];

    const int t    = threadIdx.x;
    const int lane = t & 31;
    const int wid  = t >> 5;
    const int wm   = (wid & 3) * 32;
    const int wn   = (wid >> 2) * 64;

    // global->shared load mapping (2 float4 per array per thread)
    const int lr = t >> 2;
    const int lc = (t & 3) * 4;
    const float* Ap = A + (size_t)(m0 + lr) * CC + lc;
    const float* Bp = W + (size_t)(n0 + lr) * CC + lc;

    // ldmatrix lane address components
    const int arow = (lane & 7) + ((lane >> 3) & 1) * 8;   // A: rows 0-15
    const int akw  = (lane >> 4) * 4;                      // A: k word 0/4
    const int brow = (lane & 7) + (lane >> 4) * 8;         // B: n rows (pairs of tiles)
    const int bkw  = ((lane >> 3) & 1) * 4;                // B: k word 0/4

    const uint32_t aAddr = smem_u32(&As[0][0]) + (((wm + arow) * 20 + akw) << 2);
    const uint32_t bAddr = smem_u32(&Bs[0][0]) + (((wn + brow) * 20 + bkw) << 2);

    float4 ra0 = *(const float4*)Ap;
    float4 ra1 = *(const float4*)(Ap + 64 * CC);
    float4 rb0 = *(const float4*)Bp;
    float4 rb1 = *(const float4*)(Bp + 64 * CC);

    #pragma unroll
    for (int mt = 0; mt < 2; mt++)
        #pragma unroll
        for (int nt = 0; nt < 8; nt++)
            #pragma unroll
            for (int c = 0; c < 4; c++) acc[mt][nt][c] = 0.f;

    for (int kt = 0; kt < CC / 16; kt++) {
        __syncthreads();
        As[lr][lc + 0]      = to_tf32(ra0.x); As[lr][lc + 1]      = to_tf32(ra0.y);
        As[lr][lc + 2]      = to_tf32(ra0.z); As[lr][lc + 3]      = to_tf32(ra0.w);
        As[lr + 64][lc + 0] = to_tf32(ra1.x); As[lr + 64][lc + 1] = to_tf32(ra1.y);
        As[lr + 64][lc + 2] = to_tf32(ra1.z); As[lr + 64][lc + 3] = to_tf32(ra1.w);
        Bs[lr][lc + 0]      = to_tf32(rb0.x); Bs[lr][lc + 1]      = to_tf32(rb0.y);
        Bs[lr][lc + 2]      = to_tf32(rb0.z); Bs[lr][lc + 3]      = to_tf32(rb0.w);
        Bs[lr + 64][lc + 0] = to_tf32(rb1.x); Bs[lr + 64][lc + 1] = to_tf32(rb1.y);
        Bs[lr + 64][lc + 2] = to_tf32(rb1.z); Bs[lr + 64][lc + 3] = to_tf32(rb1.w);
        __syncthreads();

        if (kt + 1 < CC / 16) {
            Ap += 16; Bp += 16;
            ra0 = *(const float4*)Ap;
            ra1 = *(const float4*)(Ap + 64 * CC);
            rb0 = *(const float4*)Bp;
            rb1 = *(const float4*)(Bp + 64 * CC);
        }

        #pragma unroll
        for (int kk = 0; kk < 2; kk++) {
            uint32_t a0[4], a1[4];
            LDSM4(a0, aAddr + kk * 32);
            LDSM4(a1, aAddr + 1280 + kk * 32);         // mt=1: +16 rows * 20 * 4B
            #pragma unroll
            for (int p = 0; p < 4; p++) {
                uint32_t b[4];
                LDSM4(b, bAddr + p * 1280 + kk * 32);  // p: +16 n-rows
                MMA_TF32(acc[0][2 * p],     a0, b[0], b[1]);
                MMA_TF32(acc[0][2 * p + 1], a0, b[2], b[3]);
                MMA_TF32(acc[1][2 * p],     a1, b[0], b[1]);
                MMA_TF32(acc[1][2 * p + 1], a1, b[2], b[3]);
            }
        }
    }
}

// ---------------------------------------------------------------------------
// Kernel 1: fused QKV projection. grid = (8, 64, 3). Scatter into [B,H,T,D].
// ---------------------------------------------------------------------------
__global__ void __launch_bounds__(256) qkv_kernel(const float* __restrict__ x,
                                                  const float* __restrict__ Wq,
                                                  const float* __restrict__ Wk,
                                                  const float* __restrict__ Wv)
{
    const int z = blockIdx.z;
    const float* W = (z == 0) ? Wq : (z == 1) ? Wk : Wv;
    float* dst     = (z == 0) ? g_Q : (z == 1) ? g_K : g_V;

    const int m0 = blockIdx.y * 128;
    const int n0 = blockIdx.x * 128;

    float acc[2][8][4];
    gemm_tf32(x, W, m0, n0, acc);

    const int lane = threadIdx.x & 31, wid = threadIdx.x >> 5;
    const int g = lane >> 2, ctid = lane & 3;
    const int wm = (wid & 3) * 32, wn = (wid >> 2) * 64;

    #pragma unroll
    for (int mt = 0; mt < 2; mt++) {
        const int m = m0 + wm + 16 * mt + g;
        const int b1 = m >> 11;
        const int t1 = m & (TT - 1);
        #pragma unroll
        for (int nt = 0; nt < 8; nt++) {
            const int n = n0 + wn + 8 * nt + 2 * ctid;
            const int h = n >> 6, d = n & 63;
            float* base = dst + ((size_t)(b1 * HH + h) * TT + t1) * DD + d;
            *(float2*)base            = make_float2(acc[mt][nt][0], acc[mt][nt][1]);
            *(float2*)(base + 8 * DD) = make_float2(acc[mt][nt][2], acc[mt][nt][3]);
        }
    }
}

// ---------------------------------------------------------------------------
// fast exp2 (FMA polynomial; inputs <= 0). Avoids MUFU throughput wall.
// ---------------------------------------------------------------------------
__device__ __forceinline__ float fexp2(float t)
{
    t = fmaxf(t, -126.0f);
    float r = t + 12582912.0f;
    int   n = __float_as_int(r) - 0x4B400000;
    float x = t - (r - 12582912.0f);
    float p = 1.33335581e-3f;
    p = fmaf(p, x, 9.61812910e-3f);
    p = fmaf(p, x, 5.55041087e-2f);
    p = fmaf(p, x, 2.40226507e-1f);
    p = fmaf(p, x, 6.93147182e-1f);
    p = fmaf(p, x, 1.0f);
    return p * __int_as_float((n + 127) << 23);
}

// ---------------------------------------------------------------------------
// Kernel 2: causal flash attention, tensor-core S and PV.
// grid = (32, 64), 128 threads (4 warps). Each warp owns 16 q-rows; softmax
// state lives in registers (shfl across the 4-lane ctid group).
// ---------------------------------------------------------------------------
#define AP 68
#define ATTN_SMEM_BYTES (4 * 64 * AP * 4)

__global__ void __launch_bounds__(128) attn_kernel()
{
    extern __shared__ float sm[];
    float* Qs = sm;                 // [64][AP]  q rows (pre-scaled, tf32)
    float* Ks = Qs + 64 * AP;       // [64][AP]  key rows
    float* Vt = Ks + 64 * AP;       // [64][AP]  V transposed: [d][key]
    float* Ps = Vt + 64 * AP;       // [64][AP]  probabilities

    const int t    = threadIdx.x;
    const int lane = t & 31;
    const int wid  = t >> 5;
    const int g    = lane >> 2;
    const int ctid = lane & 3;
    const int bh   = blockIdx.y;
    const int qi   = gridDim.x - 1 - blockIdx.x;   // heavy tiles first
    const int t0   = qi * 64;
    const float scale = 0.125f;
    const float L2E   = 1.4426950408889634f;

    const float* Qg = g_Q + (size_t)bh * TT * DD;
    const float* Kg = g_K + (size_t)bh * TT * DD;
    const float* Vg = g_V + (size_t)bh * TT * DD;

    // ldmatrix lane components (same scheme as GEMM, pad = AP)
    const int arow = (lane & 7) + ((lane >> 3) & 1) * 8;
    const int akw  = (lane >> 4) * 4;
    const int brow = (lane & 7) + (lane >> 4) * 8;
    const int bkw  = ((lane >> 3) & 1) * 4;

    const uint32_t aQ = smem_u32(Qs) + (((wid * 16 + arow) * AP + akw) << 2);
    const uint32_t aP = smem_u32(Ps) + (((wid * 16 + arow) * AP + akw) << 2);
    const uint32_t bK = smem_u32(Ks) + ((brow * AP + bkw) << 2);
    const uint32_t bV = smem_u32(Vt) + ((brow * AP + bkw) << 2);
    const uint32_t PSTRIDE = 16 * AP * 4;   // 16 rows in bytes

    // load Q tile (scaled, tf32)
    #pragma unroll
    for (int it = 0; it < 8; it++) {
        int lin = it * 128 + t;
        int r = lin >> 4, c4 = (lin & 15) * 4;
        float4 v = *(const float4*)&Qg[(size_t)(t0 + r) * DD + c4];
        Qs[r * AP + c4 + 0] = to_tf32(v.x * scale);
        Qs[r * AP + c4 + 1] = to_tf32(v.y * scale);
        Qs[r * AP + c4 + 2] = to_tf32(v.z * scale);
        Qs[r * AP + c4 + 3] = to_tf32(v.w * scale);
    }

    float o[8][4];
    #pragma unroll
    for (int nt = 0; nt < 8; nt++)
        #pragma unroll
        for (int c = 0; c < 4; c++) o[nt][c] = 0.f;
    float mA = -1e30f, mB = -1e30f, lA = 0.f, lB = 0.f;

    for (int j = 0; j <= qi; j++) {
        __syncthreads();   // previous iter's K/Vt consumers done

        // K tile: [key][d]
        #pragma unroll
        for (int it = 0; it < 8; it++) {
            int lin = it * 128 + t;
            int r = lin >> 4, c4 = (lin & 15) * 4;
            float4 v = *(const float4*)&Kg[(size_t)(j * 64 + r) * DD + c4];
            Ks[r * AP + c4 + 0] = to_tf32(v.x);
            Ks[r * AP + c4 + 1] = to_tf32(v.y);
            Ks[r * AP + c4 + 2] = to_tf32(v.z);
            Ks[r * AP + c4 + 3] = to_tf32(v.w);
        }
        // V tile, transposed into Vt[d][key] via 4x4 float4 register transpose
        {
            const int kq = (t & 15) * 4;
            #pragma unroll
            for (int i2 = 0; i2 < 2; i2++) {
                const int d4 = (t >> 4) * 4 + i2 * 32;
                float4 r0 = *(const float4*)&Vg[(size_t)(j * 64 + kq + 0) * DD + d4];
                float4 r1 = *(const float4*)&Vg[(size_t)(j * 64 + kq + 1) * DD + d4];
                float4 r2 = *(const float4*)&Vg[(size_t)(j * 64 + kq + 2) * DD + d4];
                float4 r3 = *(const float4*)&Vg[(size_t)(j * 64 + kq + 3) * DD + d4];
                *(float4*)&Vt[(d4 + 0) * AP + kq] =
                    make_float4(to_tf32(r0.x), to_tf32(r1.x), to_tf32(r2.x), to_tf32(r3.x));
                *(float4*)&Vt[(d4 + 1) * AP + kq] =
                    make_float4(to_tf32(r0.y), to_tf32(r1.y), to_tf32(r2.y), to_tf32(r3.y));
                *(float4*)&Vt[(d4 + 2) * AP + kq] =
                    make_float4(to_tf32(r0.z), to_tf32(r1.z), to_tf32(r2.z), to_tf32(r3.z));
                *(float4*)&Vt[(d4 + 3) * AP + kq] =
                    make_float4(to_tf32(r0.w), to_tf32(r1.w), to_tf32(r2.w), to_tf32(r3.w));
            }
        }
        __syncthreads();

        // ---- S = Q * K^T (warp rows x 64 keys) ----
        float s[8][4];
        #pragma unroll
        for (int nt = 0; nt < 8; nt++)
            #pragma unroll
            for (int c = 0; c < 4; c++) s[nt][c] = 0.f;

        #pragma unroll
        for (int kk = 0; kk < 8; kk++) {
            uint32_t a[4];
            LDSM4(a, aQ + kk * 32);
            #pragma unroll
            for (int p = 0; p < 4; p++) {
                uint32_t b[4];
                LDSM4(b, bK + p * PSTRIDE + kk * 32);
                MMA_TF32(s[2 * p],     a, b[0], b[1]);
                MMA_TF32(s[2 * p + 1], a, b[2], b[3]);
            }
        }

        // causal mask on the diagonal tile
        if (j == qi) {
            const int r0_ = wid * 16 + g, r8_ = r0_ + 8;
            #pragma unroll
            for (int nt = 0; nt < 8; nt++) {
                const int cb = 8 * nt + 2 * ctid;
                if (cb     > r0_) s[nt][0] = -1e30f;
                if (cb + 1 > r0_) s[nt][1] = -1e30f;
                if (cb     > r8_) s[nt][2] = -1e30f;
                if (cb + 1 > r8_) s[nt][3] = -1e30f;
            }
        }

        // ---- online softmax (register-resident, shfl over ctid group) ----
        float mx0 = -1e30f, mx8 = -1e30f;
        #pragma unroll
        for (int nt = 0; nt < 8; nt++) {
            mx0 = fmaxf(mx0, fmaxf(s[nt][0], s[nt][1]));
            mx8 = fmaxf(mx8, fmaxf(s[nt][2], s[nt][3]));
        }
        mx0 = fmaxf(mx0, __shfl_xor_sync(0xffffffffu, mx0, 1));
        mx0 = fmaxf(mx0, __shfl_xor_sync(0xffffffffu, mx0, 2));
        mx8 = fmaxf(mx8, __shfl_xor_sync(0xffffffffu, mx8, 1));
        mx8 = fmaxf(mx8, __shfl_xor_sync(0xffffffffu, mx8, 2));

        const float mn0 = fmaxf(mA, mx0), mn8 = fmaxf(mB, mx8);
        const float f0 = fexp2((mA - mn0) * L2E);
        const float f8 = fexp2((mB - mn8) * L2E);
        mA = mn0; mB = mn8;

        #pragma unroll
        for (int nt = 0; nt < 8; nt++) {
            o[nt][0] *= f0; o[nt][1] *= f0;
            o[nt][2] *= f8; o[nt][3] *= f8;
        }

        float rs0 = 0.f, rs8 = 0.f;
        const int prow0 = (wid * 16 + g) * AP;
        const int prow8 = prow0 + 8 * AP;
        #pragma unroll
        for (int nt = 0; nt < 8; nt++) {
            const float p0 = fexp2((s[nt][0] - mn0) * L2E);
            const float p1 = fexp2((s[nt][1] - mn0) * L2E);
            const float p2 = fexp2((s[nt][2] - mn8) * L2E);
            const float p3 = fexp2((s[nt][3] - mn8) * L2E);
            rs0 += p0 + p1;
            rs8 += p2 + p3;
            *(float2*)&Ps[prow0 + 8 * nt + 2 * ctid] = make_float2(to_tf32(p0), to_tf32(p1));
            *(float2*)&Ps[prow8 + 8 * nt + 2 * ctid] = make_float2(to_tf32(p2), to_tf32(p3));
        }
        rs0 += __shfl_xor_sync(0xffffffffu, rs0, 1);
        rs0 += __shfl_xor_sync(0xffffffffu, rs0, 2);
        rs8 += __shfl_xor_sync(0xffffffffu, rs8, 1);
        rs8 += __shfl_xor_sync(0xffffffffu, rs8, 2);
        lA = lA * f0 + rs0;
        lB = lB * f8 + rs8;

        __syncwarp();   // P visible to own warp's ldmatrix

        // ---- O += P * V ----
        #pragma unroll
        for (int kk = 0; kk < 8; kk++) {
            uint32_t a[4];
            LDSM4(a, aP + kk * 32);
            #pragma unroll
            for (int p = 0; p < 4; p++) {
                uint32_t b[4];
                LDSM4(b, bV + p * PSTRIDE + kk * 32);
                MMA_TF32(o[2 * p],     a, b[0], b[1]);
                MMA_TF32(o[2 * p + 1], a, b[2], b[3]);
            }
        }
    }

    // epilogue: normalize + merge heads into g_Y [B,T,C]
    const float li0 = 1.0f / lA, li8 = 1.0f / lB;
    const int b1 = bh >> 4, h = bh & 15;
    const int r0g = t0 + wid * 16 + g;
    float* y0 = g_Y + (size_t)(b1 * TT + r0g) * CC + h * 64;
    float* y8 = y0 + (size_t)8 * CC;
    #pragma unroll
    for (int nt = 0; nt < 8; nt++) {
        *(float2*)&y0[8 * nt + 2 * ctid] = make_float2(o[nt][0] * li0, o[nt][1] * li0);
        *(float2*)&y8[8 * nt + 2 * ctid] = make_float2(o[nt][2] * li8, o[nt][3] * li8);
    }
}

// ---------------------------------------------------------------------------
// Kernel 3: output projection  out = Y @ Wo^T + bo.  grid = (8, 64)
// ---------------------------------------------------------------------------
__global__ void __launch_bounds__(256) outproj_kernel(const float* __restrict__ Wo,
                                                      const float* __restrict__ bo,
                                                      float* __restrict__ out)
{
    const int m0 = blockIdx.y * 128;
    const int n0 = blockIdx.x * 128;

    float acc[2][8][4];
    gemm_tf32(g_Y, Wo, m0, n0, acc);

    const int lane = threadIdx.x & 31, wid = threadIdx.x >> 5;
    const int g = lane >> 2, ctid = lane & 3;
    const int wm = (wid & 3) * 32, wn = (wid >> 2) * 64;

    #pragma unroll
    for (int mt = 0; mt < 2; mt++) {
        const int m = m0 + wm + 16 * mt + g;
        #pragma unroll
        for (int nt = 0; nt < 8; nt++) {
            const int n = n0 + wn + 8 * nt + 2 * ctid;
            const float2 bias = *(const float2*)&bo[n];
            float* base = out + (size_t)m * CC + n;
            *(float2*)base = make_float2(acc[mt][nt][0] + bias.x, acc[mt][nt][1] + bias.y);
            *(float2*)(base + (size_t)8 * CC) =
                make_float2(acc[mt][nt][2] + bias.x, acc[mt][nt][3] + bias.y);
        }
    }
}

// ---------------------------------------------------------------------------
// Launch
// ---------------------------------------------------------------------------
extern "C" void kernel_launch(void* const* d_in, const int* in_sizes, int n_in,
                              void* d_out, int out_size)
{
    const float* x  = (const float*)d_in[0];
    const float* Wq = (const float*)d_in[1];
    const float* Wk = (const float*)d_in[2];
    const float* Wv = (const float*)d_in[3];
    const float* Wo = (const float*)d_in[4];
    const float* bo = (const float*)d_in[5];
    float* out = (float*)d_out;

    cudaFuncSetAttribute(attn_kernel, cudaFuncAttributeMaxDynamicSharedMemorySize,
                         ATTN_SMEM_BYTES);

    qkv_kernel<<<dim3(8, 64, 3), 256>>>(x, Wq, Wk, Wv);
    attn_kernel<<<dim3(32, 64), 128, ATTN_SMEM_BYTES>>>();
    outproj_kernel<<<dim3(8, 64), 256>>>(Wo, bo, out);
}

// round 6
// speedup vs baseline: 5.6460x; 1.2124x over previous
#include <cuda_runtime.h>
#include <cstdint>

// ---------------------------------------------------------------------------
// SABlock: causal MHA block. B=4, T=2048, C=1024, H=16, D=64.
// Round 5: 64x64 warp tiles (MMA:LDSM 4.0), double-buffered smem GEMM,
// 128-row attention q-tiles.
// ---------------------------------------------------------------------------

#define BB 4
#define TT 2048
#define CC 1024
#define HH 16
#define DD 64

__device__ __align__(16) float g_Q[BB * HH * TT * DD];
__device__ __align__(16) float g_K[BB * HH * TT * DD];
__device__ __align__(16) float g_V[BB * HH * TT * DD];
__device__ __align__(16) float g_Y[BB * TT * CC];

__device__ __forceinline__ float to_tf32(float x) {
    uint32_t u;
    asm("cvt.rna.tf32.f32 %0, %1;" : "=r"(u) : "f"(x));
    return __uint_as_float(u);
}
__device__ __forceinline__ uint32_t smem_u32(const void* p) {
    return (uint32_t)__cvta_generic_to_shared(p);
}

#define LDSM4(r, addr)                                                        \
    asm volatile("ldmatrix.sync.aligned.m8n8.x4.shared.b16 {%0,%1,%2,%3}, [%4];" \
                 : "=r"((r)[0]), "=r"((r)[1]), "=r"((r)[2]), "=r"((r)[3])     \
                 : "r"(addr))

#define MMA_TF32(c, a, b0_, b1_)                                              \
    asm volatile("mma.sync.aligned.m16n8k8.row.col.f32.tf32.tf32.f32 "        \
                 "{%0,%1,%2,%3},{%4,%5,%6,%7},{%8,%9},{%0,%1,%2,%3};"         \
                 : "+f"((c)[0]), "+f"((c)[1]), "+f"((c)[2]), "+f"((c)[3])     \
                 : "r"((a)[0]), "r"((a)[1]), "r"((a)[2]), "r"((a)[3]),        \
                   "r"(b0_), "r"(b1_))

// ---------------------------------------------------------------------------
// tf32 GEMM core: y[m,n] = sum_k A[m,k] * W[n,k].
// 128x128 block tile, 128 threads (4 warps, 2x2), 64x64 warp tile, K-step 16.
// Double-buffered smem, one __syncthreads per k-iter.
// ---------------------------------------------------------------------------
__device__ __forceinline__ void gemm_tf32(const float* __restrict__ A,
                                          const float* __restrict__ W,
                                          int m0, int n0, float acc[4][8][4])
{
    __shared__ float As[2][128][20];
    __shared__ float Bs[2][128][20];

    const int t    = threadIdx.x;          // 0..127
    const int lane = t & 31;
    const int wid  = t >> 5;
    const int wm   = (wid & 1) * 64;
    const int wn   = (wid >> 1) * 64;

    // global->smem staging: each thread 4 float4 per array (rows lr+32i)
    const int lr = t >> 2;                  // 0..31
    const int lc = (t & 3) * 4;             // 0,4,8,12
    const float* Ap = A + (size_t)(m0 + lr) * CC + lc;
    const float* Bp = W + (size_t)(n0 + lr) * CC + lc;

    // ldmatrix lane address components
    const int arow = (lane & 7) + ((lane >> 3) & 1) * 8;
    const int akw  = (lane >> 4) * 4;
    const int brow = (lane & 7) + (lane >> 4) * 8;
    const int bkw  = ((lane >> 3) & 1) * 4;

    const uint32_t aBase = smem_u32(&As[0][0][0]) + (((wm + arow) * 20 + akw) << 2);
    const uint32_t bBase = smem_u32(&Bs[0][0][0]) + (((wn + brow) * 20 + bkw) << 2);
    const uint32_t BUFA  = sizeof(float) * 128 * 20;   // 10240 bytes
    const uint32_t BUFB  = smem_u32(&Bs[0][0][0]) - smem_u32(&As[0][0][0]);
    (void)BUFB;

    #pragma unroll
    for (int i = 0; i < 4; i++)
        #pragma unroll
        for (int nt = 0; nt < 8; nt++)
            #pragma unroll
            for (int c = 0; c < 4; c++) acc[i][nt][c] = 0.f;

    float4 ra[4], rb[4];

    // prologue: kt = 0 into buffer 0
    #pragma unroll
    for (int i = 0; i < 4; i++) {
        ra[i] = *(const float4*)(Ap + (size_t)(32 * i) * CC);
        rb[i] = *(const float4*)(Bp + (size_t)(32 * i) * CC);
    }
    #pragma unroll
    for (int i = 0; i < 4; i++) {
        float* as = &As[0][lr + 32 * i][lc];
        as[0] = to_tf32(ra[i].x); as[1] = to_tf32(ra[i].y);
        as[2] = to_tf32(ra[i].z); as[3] = to_tf32(ra[i].w);
        float* bs = &Bs[0][lr + 32 * i][lc];
        bs[0] = to_tf32(rb[i].x); bs[1] = to_tf32(rb[i].y);
        bs[2] = to_tf32(rb[i].z); bs[3] = to_tf32(rb[i].w);
    }
    __syncthreads();

    for (int kt = 0; kt < CC / 16; kt++) {
        const int cur = kt & 1;
        const uint32_t aB = aBase + cur * BUFA;
        const uint32_t bB = bBase + cur * BUFA;

        if (kt + 1 < CC / 16) {
            const float* Ap2 = Ap + (kt + 1) * 16;
            const float* Bp2 = Bp + (kt + 1) * 16;
            #pragma unroll
            for (int i = 0; i < 4; i++) {
                ra[i] = *(const float4*)(Ap2 + (size_t)(32 * i) * CC);
                rb[i] = *(const float4*)(Bp2 + (size_t)(32 * i) * CC);
            }
        }

        #pragma unroll
        for (int kk = 0; kk < 2; kk++) {
            uint32_t a[4][4];
            #pragma unroll
            for (int i = 0; i < 4; i++)
                LDSM4(a[i], aB + i * 1280 + kk * 32);
            #pragma unroll
            for (int p = 0; p < 4; p++) {
                uint32_t b[4];
                LDSM4(b, bB + p * 1280 + kk * 32);
                #pragma unroll
                for (int i = 0; i < 4; i++) {
                    MMA_TF32(acc[i][2 * p],     a[i], b[0], b[1]);
                    MMA_TF32(acc[i][2 * p + 1], a[i], b[2], b[3]);
                }
            }
        }

        if (kt + 1 < CC / 16) {
            const int nxt = cur ^ 1;
            #pragma unroll
            for (int i = 0; i < 4; i++) {
                float* as = &As[nxt][lr + 32 * i][lc];
                as[0] = to_tf32(ra[i].x); as[1] = to_tf32(ra[i].y);
                as[2] = to_tf32(ra[i].z); as[3] = to_tf32(ra[i].w);
                float* bs = &Bs[nxt][lr + 32 * i][lc];
                bs[0] = to_tf32(rb[i].x); bs[1] = to_tf32(rb[i].y);
                bs[2] = to_tf32(rb[i].z); bs[3] = to_tf32(rb[i].w);
            }
        }
        __syncthreads();
    }
}

// ---------------------------------------------------------------------------
// Kernel 1: fused QKV projection. grid = (8, 64, 3), 128 threads.
// ---------------------------------------------------------------------------
__global__ void __launch_bounds__(128) qkv_kernel(const float* __restrict__ x,
                                                  const float* __restrict__ Wq,
                                                  const float* __restrict__ Wk,
                                                  const float* __restrict__ Wv)
{
    const int z = blockIdx.z;
    const float* W = (z == 0) ? Wq : (z == 1) ? Wk : Wv;
    float* dst     = (z == 0) ? g_Q : (z == 1) ? g_K : g_V;

    const int m0 = blockIdx.y * 128;
    const int n0 = blockIdx.x * 128;

    float acc[4][8][4];
    gemm_tf32(x, W, m0, n0, acc);

    const int lane = threadIdx.x & 31, wid = threadIdx.x >> 5;
    const int g = lane >> 2, ctid = lane & 3;
    const int wm = (wid & 1) * 64, wn = (wid >> 1) * 64;

    #pragma unroll
    for (int i = 0; i < 4; i++) {
        const int m = m0 + wm + 16 * i + g;
        const int b1 = m >> 11;
        const int t1 = m & (TT - 1);
        #pragma unroll
        for (int nt = 0; nt < 8; nt++) {
            const int n = n0 + wn + 8 * nt + 2 * ctid;
            const int h = n >> 6, d = n & 63;
            float* base = dst + ((size_t)(b1 * HH + h) * TT + t1) * DD + d;
            *(float2*)base            = make_float2(acc[i][nt][0], acc[i][nt][1]);
            *(float2*)(base + 8 * DD) = make_float2(acc[i][nt][2], acc[i][nt][3]);
        }
    }
}

// ---------------------------------------------------------------------------
// fast exp2 (FMA polynomial; inputs <= 0). Avoids MUFU throughput wall.
// ---------------------------------------------------------------------------
__device__ __forceinline__ float fexp2(float t)
{
    t = fmaxf(t, -126.0f);
    float r = t + 12582912.0f;
    int   n = __float_as_int(r) - 0x4B400000;
    float x = t - (r - 12582912.0f);
    float p = 1.33335581e-3f;
    p = fmaf(p, x, 9.61812910e-3f);
    p = fmaf(p, x, 5.55041087e-2f);
    p = fmaf(p, x, 2.40226507e-1f);
    p = fmaf(p, x, 6.93147182e-1f);
    p = fmaf(p, x, 1.0f);
    return p * __int_as_float((n + 127) << 23);
}

// ---------------------------------------------------------------------------
// Kernel 2: causal flash attention. grid = (16, 64), 256 threads (8 warps).
// 128 q-rows per block, 64-key tiles. Each warp owns 16 q-rows; softmax state
// in registers (shfl over ctid group).
// ---------------------------------------------------------------------------
#define AP 68
#define ATTN_SMEM_BYTES ((128 + 64 + 64 + 128) * AP * 4)

__global__ void __launch_bounds__(256) attn_kernel()
{
    extern __shared__ float sm[];
    float* Qs = sm;                  // [128][AP]  q rows (pre-scaled, tf32)
    float* Ks = Qs + 128 * AP;       // [64][AP]   key rows
    float* Vt = Ks + 64 * AP;        // [64][AP]   V transposed: [d][key]
    float* Ps = Vt + 64 * AP;        // [128][AP]  probabilities

    const int t    = threadIdx.x;
    const int lane = t & 31;
    const int wid  = t >> 5;             // 0..7
    const int g    = lane >> 2;
    const int ctid = lane & 3;
    const int bh   = blockIdx.y;
    const int qi   = gridDim.x - 1 - blockIdx.x;   // heavy tiles first
    const int t0   = qi * 128;
    const float scale = 0.125f;
    const float L2E   = 1.4426950408889634f;

    const float* Qg = g_Q + (size_t)bh * TT * DD;
    const float* Kg = g_K + (size_t)bh * TT * DD;
    const float* Vg = g_V + (size_t)bh * TT * DD;

    const int arow = (lane & 7) + ((lane >> 3) & 1) * 8;
    const int akw  = (lane >> 4) * 4;
    const int brow = (lane & 7) + (lane >> 4) * 8;
    const int bkw  = ((lane >> 3) & 1) * 4;

    const uint32_t aQ = smem_u32(Qs) + (((wid * 16 + arow) * AP + akw) << 2);
    const uint32_t aP = smem_u32(Ps) + (((wid * 16 + arow) * AP + akw) << 2);
    const uint32_t bK = smem_u32(Ks) + ((brow * AP + bkw) << 2);
    const uint32_t bV = smem_u32(Vt) + ((brow * AP + bkw) << 2);
    const uint32_t PSTRIDE = 16 * AP * 4;

    // load Q tile (scaled, tf32): 128 rows x 64 cols
    #pragma unroll
    for (int it = 0; it < 8; it++) {
        int lin = it * 256 + t;
        int r = lin >> 4, c4 = (lin & 15) * 4;
        float4 v = *(const float4*)&Qg[(size_t)(t0 + r) * DD + c4];
        Qs[r * AP + c4 + 0] = to_tf32(v.x * scale);
        Qs[r * AP + c4 + 1] = to_tf32(v.y * scale);
        Qs[r * AP + c4 + 2] = to_tf32(v.z * scale);
        Qs[r * AP + c4 + 3] = to_tf32(v.w * scale);
    }

    float o[8][4];
    #pragma unroll
    for (int nt = 0; nt < 8; nt++)
        #pragma unroll
        for (int c = 0; c < 4; c++) o[nt][c] = 0.f;
    float mA = -1e30f, mB = -1e30f, lA = 0.f, lB = 0.f;

    const int r0g = t0 + wid * 16 + g;       // global q row (first frag)
    const int r8g = r0g + 8;
    const int jmax = 2 * qi + 1;

    for (int j = 0; j <= jmax; j++) {
        __syncthreads();   // previous iter's K/Vt consumers done

        // K tile: 64 x 64
        #pragma unroll
        for (int it = 0; it < 4; it++) {
            int lin = it * 256 + t;
            int r = lin >> 4, c4 = (lin & 15) * 4;
            float4 v = *(const float4*)&Kg[(size_t)(j * 64 + r) * DD + c4];
            Ks[r * AP + c4 + 0] = to_tf32(v.x);
            Ks[r * AP + c4 + 1] = to_tf32(v.y);
            Ks[r * AP + c4 + 2] = to_tf32(v.z);
            Ks[r * AP + c4 + 3] = to_tf32(v.w);
        }
        // V tile transposed: each thread a 4x4 block
        {
            const int kq = (t & 15) * 4;
            const int d4 = (t >> 4) * 4;
            float4 r0 = *(const float4*)&Vg[(size_t)(j * 64 + kq + 0) * DD + d4];
            float4 r1 = *(const float4*)&Vg[(size_t)(j * 64 + kq + 1) * DD + d4];
            float4 r2 = *(const float4*)&Vg[(size_t)(j * 64 + kq + 2) * DD + d4];
            float4 r3 = *(const float4*)&Vg[(size_t)(j * 64 + kq + 3) * DD + d4];
            *(float4*)&Vt[(d4 + 0) * AP + kq] =
                make_float4(to_tf32(r0.x), to_tf32(r1.x), to_tf32(r2.x), to_tf32(r3.x));
            *(float4*)&Vt[(d4 + 1) * AP + kq] =
                make_float4(to_tf32(r0.y), to_tf32(r1.y), to_tf32(r2.y), to_tf32(r3.y));
            *(float4*)&Vt[(d4 + 2) * AP + kq] =
                make_float4(to_tf32(r0.z), to_tf32(r1.z), to_tf32(r2.z), to_tf32(r3.z));
            *(float4*)&Vt[(d4 + 3) * AP + kq] =
                make_float4(to_tf32(r0.w), to_tf32(r1.w), to_tf32(r2.w), to_tf32(r3.w));
        }
        __syncthreads();

        // ---- S = Q * K^T (16 warp rows x 64 keys) ----
        float s[8][4];
        #pragma unroll
        for (int nt = 0; nt < 8; nt++)
            #pragma unroll
            for (int c = 0; c < 4; c++) s[nt][c] = 0.f;

        #pragma unroll
        for (int kk = 0; kk < 8; kk++) {
            uint32_t a[4];
            LDSM4(a, aQ + kk * 32);
            #pragma unroll
            for (int p = 0; p < 4; p++) {
                uint32_t b[4];
                LDSM4(b, bK + p * PSTRIDE + kk * 32);
                MMA_TF32(s[2 * p],     a, b[0], b[1]);
                MMA_TF32(s[2 * p + 1], a, b[2], b[3]);
            }
        }

        // causal mask: only the last two k-tiles can cross the diagonal
        if (j >= 2 * qi) {
            const int kb = j * 64;
            #pragma unroll
            for (int nt = 0; nt < 8; nt++) {
                const int cg = kb + 8 * nt + 2 * ctid;
                if (cg     > r0g) s[nt][0] = -1e30f;
                if (cg + 1 > r0g) s[nt][1] = -1e30f;
                if (cg     > r8g) s[nt][2] = -1e30f;
                if (cg + 1 > r8g) s[nt][3] = -1e30f;
            }
        }

        // ---- online softmax (register-resident) ----
        float mx0 = -1e30f, mx8 = -1e30f;
        #pragma unroll
        for (int nt = 0; nt < 8; nt++) {
            mx0 = fmaxf(mx0, fmaxf(s[nt][0], s[nt][1]));
            mx8 = fmaxf(mx8, fmaxf(s[nt][2], s[nt][3]));
        }
        mx0 = fmaxf(mx0, __shfl_xor_sync(0xffffffffu, mx0, 1));
        mx0 = fmaxf(mx0, __shfl_xor_sync(0xffffffffu, mx0, 2));
        mx8 = fmaxf(mx8, __shfl_xor_sync(0xffffffffu, mx8, 1));
        mx8 = fmaxf(mx8, __shfl_xor_sync(0xffffffffu, mx8, 2));

        const float mn0 = fmaxf(mA, mx0), mn8 = fmaxf(mB, mx8);
        const float f0 = fexp2((mA - mn0) * L2E);
        const float f8 = fexp2((mB - mn8) * L2E);
        mA = mn0; mB = mn8;

        #pragma unroll
        for (int nt = 0; nt < 8; nt++) {
            o[nt][0] *= f0; o[nt][1] *= f0;
            o[nt][2] *= f8; o[nt][3] *= f8;
        }

        float rs0 = 0.f, rs8 = 0.f;
        const int prow0 = (wid * 16 + g) * AP;
        const int prow8 = prow0 + 8 * AP;
        #pragma unroll
        for (int nt = 0; nt < 8; nt++) {
            const float p0 = fexp2((s[nt][0] - mn0) * L2E);
            const float p1 = fexp2((s[nt][1] - mn0) * L2E);
            const float p2 = fexp2((s[nt][2] - mn8) * L2E);
            const float p3 = fexp2((s[nt][3] - mn8) * L2E);
            rs0 += p0 + p1;
            rs8 += p2 + p3;
            *(float2*)&Ps[prow0 + 8 * nt + 2 * ctid] = make_float2(to_tf32(p0), to_tf32(p1));
            *(float2*)&Ps[prow8 + 8 * nt + 2 * ctid] = make_float2(to_tf32(p2), to_tf32(p3));
        }
        rs0 += __shfl_xor_sync(0xffffffffu, rs0, 1);
        rs0 += __shfl_xor_sync(0xffffffffu, rs0, 2);
        rs8 += __shfl_xor_sync(0xffffffffu, rs8, 1);
        rs8 += __shfl_xor_sync(0xffffffffu, rs8, 2);
        lA = lA * f0 + rs0;
        lB = lB * f8 + rs8;

        __syncwarp();   // P visible to own warp's ldmatrix

        // ---- O += P * V ----
        #pragma unroll
        for (int kk = 0; kk < 8; kk++) {
            uint32_t a[4];
            LDSM4(a, aP + kk * 32);
            #pragma unroll
            for (int p = 0; p < 4; p++) {
                uint32_t b[4];
                LDSM4(b, bV + p * PSTRIDE + kk * 32);
                MMA_TF32(o[2 * p],     a, b[0], b[1]);
                MMA_TF32(o[2 * p + 1], a, b[2], b[3]);
            }
        }
    }

    // epilogue: normalize + merge heads into g_Y [B,T,C]
    const float li0 = 1.0f / lA, li8 = 1.0f / lB;
    const int b1 = bh >> 4, h = bh & 15;
    float* y0 = g_Y + (size_t)(b1 * TT + r0g) * CC + h * 64;
    float* y8 = y0 + (size_t)8 * CC;
    #pragma unroll
    for (int nt = 0; nt < 8; nt++) {
        *(float2*)&y0[8 * nt + 2 * ctid] = make_float2(o[nt][0] * li0, o[nt][1] * li0);
        *(float2*)&y8[8 * nt + 2 * ctid] = make_float2(o[nt][2] * li8, o[nt][3] * li8);
    }
}

// ---------------------------------------------------------------------------
// Kernel 3: output projection  out = Y @ Wo^T + bo.  grid = (8, 64), 128 thr.
// ---------------------------------------------------------------------------
__global__ void __launch_bounds__(128) outproj_kernel(const float* __restrict__ Wo,
                                                      const float* __restrict__ bo,
                                                      float* __restrict__ out)
{
    const int m0 = blockIdx.y * 128;
    const int n0 = blockIdx.x * 128;

    float acc[4][8][4];
    gemm_tf32(g_Y, Wo, m0, n0, acc);

    const int lane = threadIdx.x & 31, wid = threadIdx.x >> 5;
    const int g = lane >> 2, ctid = lane & 3;
    const int wm = (wid & 1) * 64, wn = (wid >> 1) * 64;

    #pragma unroll
    for (int i = 0; i < 4; i++) {
        const int m = m0 + wm + 16 * i + g;
        #pragma unroll
        for (int nt = 0; nt < 8; nt++) {
            const int n = n0 + wn + 8 * nt + 2 * ctid;
            const float2 bias = *(const float2*)&bo[n];
            float* base = out + (size_t)m * CC + n;
            *(float2*)base = make_float2(acc[i][nt][0] + bias.x, acc[i][nt][1] + bias.y);
            *(float2*)(base + (size_t)8 * CC) =
                make_float2(acc[i][nt][2] + bias.x, acc[i][nt][3] + bias.y);
        }
    }
}

// ---------------------------------------------------------------------------
// Launch
// ---------------------------------------------------------------------------
extern "C" void kernel_launch(void* const* d_in, const int* in_sizes, int n_in,
                              void* d_out, int out_size)
{
    const float* x  = (const float*)d_in[0];
    const float* Wq = (const float*)d_in[1];
    const float* Wk = (const float*)d_in[2];
    const float* Wv = (const float*)d_in[3];
    const float* Wo = (const float*)d_in[4];
    const float* bo = (const float*)d_in[5];
    float* out = (float*)d_out;

    cudaFuncSetAttribute(attn_kernel, cudaFuncAttributeMaxDynamicSharedMemorySize,
                         ATTN_SMEM_BYTES);

    qkv_kernel<<<dim3(8, 64, 3), 128>>>(x, Wq, Wk, Wv);
    attn_kernel<<<dim3(16, 64), 256, ATTN_SMEM_BYTES>>>();
    outproj_kernel<<<dim3(8, 64), 128>>>(Wo, bo, out);
}